// round 6
// baseline (speedup 1.0000x reference)
#include <cuda_runtime.h>

// Problem constants: x (16,800,256), mu (64,256), prec (64) -> out (16, 64*256)
#define BB 16
#define TT 800
#define DD 256
#define KK 64
#define NSLOT 9   // 8 blocks of 96 rows + 1 block of 32 rows per batch
#define PX 68     // smem pitch for sx/smu (16B-aligned rows, conflict-free)
#define PG 65     // smem pitch for sG (kills STS bank conflicts in dump)

typedef unsigned long long ull;

// ---------------- scratch (device globals; fully overwritten every call) -------
__device__ float g_P[BB * NSLOT * KK * DD];   // per-slot pool partials, 9.4MB
__device__ float g_Ssl[BB * NSLOT * KK];      // per-slot softmax sums
__device__ int   g_tkt[BB];                   // per-batch completion tickets (self-resetting)

// ---------------- f32x2 helpers -------------------------------------------------
__device__ __forceinline__ ull pack2(float lo, float hi) {
    ull r; asm("mov.b64 %0,{%1,%2};" : "=l"(r) : "f"(lo), "f"(hi)); return r;
}
__device__ __forceinline__ ull fma2(ull a, ull b, ull c) {
    ull d; asm("fma.rn.f32x2 %0,%1,%2,%3;" : "=l"(d) : "l"(a), "l"(b), "l"(c)); return d;
}
__device__ __forceinline__ float2 unpack2(ull v) {
    float2 f; asm("mov.b64 {%0,%1},%2;" : "=f"(f.x), "=f"(f.y) : "l"(v)); return f;
}

union F4 { float4 f; ull u[2]; };

// ---------------- fused body: llk GEMM + softmax + pool GEMM + tail reduce ------
template<int NR>
__device__ __forceinline__ void fused_body(int b, int slot, int trow0,
                                           const float* __restrict__ x,
                                           const float* __restrict__ mu,
                                           const float* __restrict__ prec,
                                           float* __restrict__ out) {
    constexpr int RT  = NR / 16;   // staging loads per thread
    constexpr int RPW = NR / 8;    // rows per warp (phase B)
    constexpr int RL  = NR / 32;   // rows per lane (phase A compute)

    extern __shared__ char sm[];
    float* sx    = (float*)sm;             // NR*PX
    float* smu   = sx + NR * PX;           // 64*PX
    float* sr    = smu + 64 * PX;          // NR*64
    float* sxsq  = sr + NR * 64;           // NR
    float* smusq = sxsq + NR;              // 64
    float* sS    = smusq + 64;             // 8*64 per-warp softmax-sum partials
    float*  sG = sx;                       // phase B overlay: NR*PG <= NR*PX
    float4* xs = (float4*)sx;              // phase C overlay: 16*64 f4 = 16KB
    __shared__ int s_last;

    int tid  = threadIdx.x;
    int lane = tid & 31;
    int w    = tid >> 5;

    const float4* x4  = (const float4*)x;
    const float4* mu4 = (const float4*)mu;

    ull acc[RL * 8];
    #pragma unroll
    for (int i = 0; i < RL * 8; i++) acc[i] = 0ull;
    float myxsq[RT];
    #pragma unroll
    for (int i = 0; i < RT; i++) myxsq[i] = 0.f;
    float mymusq[4] = {0.f, 0.f, 0.f, 0.f};

    // prefetch chunk 0 (staging layout: 16 threads per row, j = tid&15)
    float4 px[RT], pm[4];
    #pragma unroll
    for (int ii = 0; ii < RT; ii++) {
        int idx = tid + 256 * ii;
        px[ii] = x4[(trow0 + (idx >> 4)) * 64 + (idx & 15)];
    }
    #pragma unroll
    for (int ii = 0; ii < 4; ii++) {
        int idx = tid + 256 * ii;
        pm[ii] = mu4[(idx >> 4) * 64 + (idx & 15)];
    }

    // ---- Phase A: distance GEMM over 4 chunks of 64 d ----
    for (int c = 0; c < 4; c++) {
        __syncthreads();
        #pragma unroll
        for (int ii = 0; ii < RT; ii++) {
            int idx = tid + 256 * ii;
            int r = idx >> 4, j = idx & 15;
            float4 v = px[ii];
            myxsq[ii] += v.x * v.x + v.y * v.y + v.z * v.z + v.w * v.w;
            *(float4*)(sx + r * PX + 4 * j) = v;
        }
        #pragma unroll
        for (int ii = 0; ii < 4; ii++) {
            int idx = tid + 256 * ii;
            int r = idx >> 4, j = idx & 15;
            float4 m = pm[ii];
            mymusq[ii] += m.x * m.x + m.y * m.y + m.z * m.z + m.w * m.w;
            *(float4*)(smu + r * PX + 4 * j) = m;
        }
        __syncthreads();
        if (c < 3) {   // prefetch next chunk while computing this one
            #pragma unroll
            for (int ii = 0; ii < RT; ii++) {
                int idx = tid + 256 * ii;
                px[ii] = x4[(trow0 + (idx >> 4)) * 64 + (c + 1) * 16 + (idx & 15)];
            }
            #pragma unroll
            for (int ii = 0; ii < 4; ii++) {
                int idx = tid + 256 * ii;
                pm[ii] = mu4[(idx >> 4) * 64 + (c + 1) * 16 + (idx & 15)];
            }
        }
        // compute: 16 iterations of 4 d (2 d-pairs) each
        #pragma unroll 2
        for (int q = 0; q < 16; q++) {
            F4 mv[8], xv[RL];
            #pragma unroll
            for (int j = 0; j < 8; j++)
                mv[j].f = *(const float4*)(smu + (w * 8 + j) * PX + 4 * q);  // broadcast
            #pragma unroll
            for (int i = 0; i < RL; i++)
                xv[i].f = *(const float4*)(sx + (lane + 32 * i) * PX + 4 * q);
            #pragma unroll
            for (int i = 0; i < RL; i++)
                #pragma unroll
                for (int j = 0; j < 8; j++) {
                    acc[i * 8 + j] = fma2(xv[i].u[0], mv[j].u[0], acc[i * 8 + j]);
                    acc[i * 8 + j] = fma2(xv[i].u[1], mv[j].u[1], acc[i * 8 + j]);
                }
        }
    }

    // reduce xsq / musq across the 16 threads sharing a staging row
    #pragma unroll
    for (int o = 1; o < 16; o <<= 1) {
        #pragma unroll
        for (int ii = 0; ii < RT; ii++)
            myxsq[ii] += __shfl_xor_sync(0xffffffffu, myxsq[ii], o);
        #pragma unroll
        for (int ii = 0; ii < 4; ii++)
            mymusq[ii] += __shfl_xor_sync(0xffffffffu, mymusq[ii], o);
    }
    __syncthreads();   // everyone done reading sx before sG overlay
    if ((tid & 15) == 0) {
        #pragma unroll
        for (int ii = 0; ii < RT; ii++) sxsq[(tid >> 4) + 16 * ii] = myxsq[ii];
        #pragma unroll
        for (int ii = 0; ii < 4; ii++)  smusq[(tid >> 4) + 16 * ii] = mymusq[ii];
    }

    // dump G tile (overlay on sx, pitch PG)
    #pragma unroll
    for (int i = 0; i < RL; i++) {
        int row = lane + 32 * i;
        #pragma unroll
        for (int j = 0; j < 8; j++) {
            float2 v = unpack2(acc[i * 8 + j]);
            sG[row * PG + w * 8 + j] = v.x + v.y;
        }
    }
    __syncthreads();

    // ---- Phase B: softmax over K, r -> sr, per-warp S partials -> sS ----
    {
        float p0 = prec[lane], p1 = prec[lane + 32];
        float pp0 = p0 * p0, pp1 = p1 * p1;
        float mq0 = smusq[lane], mq1 = smusq[lane + 32];
        float ss0 = 0.f, ss1 = 0.f;
        #pragma unroll
        for (int rr = 0; rr < RPW; rr++) {
            int row = w * RPW + rr;
            float xq = sxsq[row];
            float G0 = sG[row * PG + lane];
            float G1 = sG[row * PG + lane + 32];
            float l0 = -pp0 * (xq - 2.f * G0 + mq0);
            float l1 = -pp1 * (xq - 2.f * G1 + mq1);
            float m = fmaxf(l0, l1);
            #pragma unroll
            for (int o = 16; o; o >>= 1) m = fmaxf(m, __shfl_xor_sync(0xffffffffu, m, o));
            float e0 = __expf(l0 - m), e1 = __expf(l1 - m);
            float s = e0 + e1;
            #pragma unroll
            for (int o = 16; o; o >>= 1) s += __shfl_xor_sync(0xffffffffu, s, o);
            float inv = 1.f / s;
            float r0 = e0 * inv, r1 = e1 * inv;
            sr[row * 64 + lane]      = r0;
            sr[row * 64 + lane + 32] = r1;
            ss0 += r0; ss1 += r1;
        }
        sS[w * 64 + lane]      = ss0;
        sS[w * 64 + lane + 32] = ss1;
    }
    __syncthreads();
    if (tid < 64) {      // cross-warp reduce, single deterministic slot write
        float S = 0.f;
        #pragma unroll
        for (int ww = 0; ww < 8; ww++) S += sS[ww * 64 + tid];
        g_Ssl[(b * NSLOT + slot) * 64 + tid] = S;
    }

    // ---- Phase C: pool GEMM, thread tile 8k x 8d, reg-prefetch pipeline ----
    ull acc2[32];
    #pragma unroll
    for (int i = 0; i < 32; i++) acc2[i] = 0ull;

    float4 pc[4];
    #pragma unroll
    for (int ii = 0; ii < 4; ii++) {
        int idx = tid + 256 * ii;
        pc[ii] = x4[(trow0 + (idx >> 6)) * 64 + (idx & 63)];
    }

    for (int st = 0; st < NR / 16; st++) {
        __syncthreads();
        #pragma unroll
        for (int ii = 0; ii < 4; ii++) xs[tid + 256 * ii] = pc[ii];
        __syncthreads();
        if (st < NR / 16 - 1) {
            #pragma unroll
            for (int ii = 0; ii < 4; ii++) {
                int idx = tid + 256 * ii;
                pc[ii] = x4[(trow0 + (st + 1) * 16 + (idx >> 6)) * 64 + (idx & 63)];
            }
        }
        #pragma unroll
        for (int tt = 0; tt < 16; tt++) {
            const float* rk = &sr[(st * 16 + tt) * 64 + w * 8];
            ull rp[4];
            #pragma unroll
            for (int m = 0; m < 4; m++)
                rp[m] = *(const ull*)(rk + 2 * m);    // broadcast LDS.64
            F4 xa, xb;
            xa.f = xs[tt * 64 + lane];
            xb.f = xs[tt * 64 + 32 + lane];
            #pragma unroll
            for (int m = 0; m < 4; m++) {
                float2 rr = unpack2(rp[m]);
                ull r2a = pack2(rr.x, rr.x);
                ull r2b = pack2(rr.y, rr.y);
                int ka = (2 * m) * 4, kb = (2 * m + 1) * 4;
                acc2[ka + 0] = fma2(r2a, xa.u[0], acc2[ka + 0]);
                acc2[ka + 1] = fma2(r2a, xa.u[1], acc2[ka + 1]);
                acc2[ka + 2] = fma2(r2a, xb.u[0], acc2[ka + 2]);
                acc2[ka + 3] = fma2(r2a, xb.u[1], acc2[ka + 3]);
                acc2[kb + 0] = fma2(r2b, xa.u[0], acc2[kb + 0]);
                acc2[kb + 1] = fma2(r2b, xa.u[1], acc2[kb + 1]);
                acc2[kb + 2] = fma2(r2b, xb.u[0], acc2[kb + 2]);
                acc2[kb + 3] = fma2(r2b, xb.u[1], acc2[kb + 3]);
            }
        }
    }

    // plain STG of the partial tile into this block's private slot (no atomics)
    float4* pslot = (float4*)(g_P + (b * NSLOT + slot) * (KK * DD));
    #pragma unroll
    for (int kk = 0; kk < 8; kk++) {
        int kr = (w * 8 + kk) * 64;    // float4 row pitch = 64
        F4 v0, v1;
        v0.u[0] = acc2[kk * 4 + 0]; v0.u[1] = acc2[kk * 4 + 1];
        v1.u[0] = acc2[kk * 4 + 2]; v1.u[1] = acc2[kk * 4 + 3];
        pslot[kr + lane]      = v0.f;   // d = 4*lane
        pslot[kr + 32 + lane] = v1.f;   // d = 128 + 4*lane
    }

    // ---- Tail: last block of this batch reduces slots + finalizes out[b] ----
    __threadfence();                       // publish slot P + S before ticket
    if (tid == 0) {
        int old = atomicAdd(&g_tkt[b], 1);
        s_last = (old == NSLOT - 1) ? 1 : 0;
    }
    __syncthreads();
    if (s_last) {
        __threadfence();                   // observe all other slots' data

        // S[k] = sum over 9 slots (deterministic order) -> smem
        if (tid < 64) {
            float S = 0.f;
            const float* ss = g_Ssl + b * NSLOT * 64 + tid;
            #pragma unroll
            for (int s = 0; s < NSLOT; s++) S += ss[s * 64];
            sS[tid] = S;
        }
        __syncthreads();

        const float4* pb = (const float4*)(g_P + b * NSLOT * KK * DD);
        float4* ob = (float4*)out + b * 4096;
        #pragma unroll
        for (int h = 0; h < 16; h++) {
            int i = tid + 256 * h;         // f4 index within batch [0,4096)
            int k = i >> 6;
            float S = sS[k];
            float inv = 1.f / (S + 1e-9f);
            float4 a = make_float4(0.f, 0.f, 0.f, 0.f);
            #pragma unroll
            for (int s = 0; s < NSLOT; s++) {
                float4 v = pb[s * 4096 + i];
                a.x += v.x; a.y += v.y; a.z += v.z; a.w += v.w;
            }
            float4 m = mu4[i];             // i == k*64 + d4 matches mu layout
            float4 o;
            o.x = (a.x - m.x * S) * inv;
            o.y = (a.y - m.y * S) * inv;
            o.z = (a.z - m.z * S) * inv;
            o.w = (a.w - m.w * S) * inv;
            ob[i] = o;
        }
        __syncthreads();
        if (tid == 0) g_tkt[b] = 0;        // reset for next graph replay
    }
}

__global__ __launch_bounds__(256, 1)
void fused_kernel(const float* __restrict__ x, const float* __restrict__ mu,
                  const float* __restrict__ prec, float* __restrict__ out) {
    int bx = blockIdx.x;
    if (bx < 128) {
        int b = bx >> 3, slot = bx & 7;
        fused_body<96>(b, slot, b * TT + slot * 96, x, mu, prec, out);
    } else {
        int b = bx - 128;
        fused_body<32>(b, 8, b * TT + 768, x, mu, prec, out);
    }
}

// smem: (96*68 + 64*68 + 96*64 + 96 + 64 + 512) * 4 = 70784 bytes
#define FUSED_SMEM 70784

// ---------------- launcher --------------------------------------------------------
extern "C" void kernel_launch(void* const* d_in, const int* in_sizes, int n_in,
                              void* d_out, int out_size) {
    const float* x    = (const float*)d_in[0];
    const float* mu   = (const float*)d_in[1];
    const float* prec = (const float*)d_in[2];
    float* out = (float*)d_out;

    cudaFuncSetAttribute(fused_kernel, cudaFuncAttributeMaxDynamicSharedMemorySize,
                         FUSED_SMEM);

    fused_kernel<<<144, 256, FUSED_SMEM>>>(x, mu, prec, out);
}

// round 7
// speedup vs baseline: 1.1781x; 1.1781x over previous
#include <cuda_runtime.h>

// Problem constants: x (16,800,256), mu (64,256), prec (64) -> out (16, 64*256)
#define BB 16
#define TT 800
#define DD 256
#define KK 64
#define NSLOT 9   // 8 blocks of 96 rows + 1 block of 32 rows per batch
#define PX 68     // smem pitch for sx/smu (16B-aligned rows, conflict-free)
#define PG 65     // smem pitch for sG (kills STS bank conflicts in dump)

typedef unsigned long long ull;

// ---------------- scratch (device globals; fully overwritten every call) -------
__device__ float g_P[BB * NSLOT * KK * DD];   // per-slot pool partials, 9.4MB
__device__ float g_Ssl[BB * NSLOT * KK];      // per-slot softmax sums

// ---------------- f32x2 helpers -------------------------------------------------
__device__ __forceinline__ ull pack2(float lo, float hi) {
    ull r; asm("mov.b64 %0,{%1,%2};" : "=l"(r) : "f"(lo), "f"(hi)); return r;
}
__device__ __forceinline__ ull fma2(ull a, ull b, ull c) {
    ull d; asm("fma.rn.f32x2 %0,%1,%2,%3;" : "=l"(d) : "l"(a), "l"(b), "l"(c)); return d;
}
__device__ __forceinline__ float2 unpack2(ull v) {
    float2 f; asm("mov.b64 {%0,%1},%2;" : "=f"(f.x), "=f"(f.y) : "l"(v)); return f;
}
__device__ __forceinline__ ull mk_evict_last_policy() {
    ull pol;
    asm("createpolicy.fractional.L2::evict_last.b64 %0, 1.0;" : "=l"(pol));
    return pol;
}
__device__ __forceinline__ void stg_el_f4(float4* p, float x, float y, float z,
                                          float w, ull pol) {
    asm volatile("st.global.L2::cache_hint.v4.f32 [%0], {%1,%2,%3,%4}, %5;"
                 :: "l"(p), "f"(x), "f"(y), "f"(z), "f"(w), "l"(pol) : "memory");
}

union F4 { float4 f; ull u[2]; };

// ---------------- fused body: llk GEMM + softmax + pool GEMM --------------------
template<int NR>
__device__ __forceinline__ void fused_body(int b, int slot, int trow0,
                                           const float* __restrict__ x,
                                           const float* __restrict__ mu,
                                           const float* __restrict__ prec) {
    constexpr int RT  = NR / 16;   // staging loads per thread
    constexpr int RPW = NR / 8;    // rows per warp (phase B)
    constexpr int RL  = NR / 32;   // rows per lane (phase A compute)
    constexpr int NST = NR / 16;   // phase C stages
    // phase C double-buffer offsets (bytes); NR=32 must dodge live sr region
    constexpr int XS1_OFF = (NR >= 96) ? 16384 : 40960;

    extern __shared__ char sm[];
    float* sx    = (float*)sm;             // NR*PX
    float* smu   = sx + NR * PX;           // 64*PX
    float* sr    = smu + 64 * PX;          // NR*64
    float* sxsq  = sr + NR * 64;           // NR
    float* smusq = sxsq + NR;              // 64
    float* sS    = smusq + 64;             // 8*64 per-warp softmax-sum partials
    float*  sG = sx;                       // phase B overlay: NR*PG <= NR*PX

    int tid  = threadIdx.x;
    int lane = tid & 31;
    int w    = tid >> 5;

    const float4* x4  = (const float4*)x;
    const float4* mu4 = (const float4*)mu;

    ull acc[RL * 8];
    #pragma unroll
    for (int i = 0; i < RL * 8; i++) acc[i] = 0ull;
    float myxsq[RT];
    #pragma unroll
    for (int i = 0; i < RT; i++) myxsq[i] = 0.f;
    float mymusq[4] = {0.f, 0.f, 0.f, 0.f};

    // prefetch chunk 0 (staging layout: 16 threads per row, j = tid&15)
    float4 px[RT], pm[4];
    #pragma unroll
    for (int ii = 0; ii < RT; ii++) {
        int idx = tid + 256 * ii;
        px[ii] = x4[(trow0 + (idx >> 4)) * 64 + (idx & 15)];
    }
    #pragma unroll
    for (int ii = 0; ii < 4; ii++) {
        int idx = tid + 256 * ii;
        pm[ii] = mu4[(idx >> 4) * 64 + (idx & 15)];
    }

    // ---- Phase A: distance GEMM over 4 chunks of 64 d ----
    for (int c = 0; c < 4; c++) {
        __syncthreads();
        #pragma unroll
        for (int ii = 0; ii < RT; ii++) {
            int idx = tid + 256 * ii;
            int r = idx >> 4, j = idx & 15;
            float4 v = px[ii];
            myxsq[ii] += v.x * v.x + v.y * v.y + v.z * v.z + v.w * v.w;
            *(float4*)(sx + r * PX + 4 * j) = v;
        }
        #pragma unroll
        for (int ii = 0; ii < 4; ii++) {
            int idx = tid + 256 * ii;
            int r = idx >> 4, j = idx & 15;
            float4 m = pm[ii];
            mymusq[ii] += m.x * m.x + m.y * m.y + m.z * m.z + m.w * m.w;
            *(float4*)(smu + r * PX + 4 * j) = m;
        }
        __syncthreads();
        if (c < 3) {   // prefetch next chunk while computing this one
            #pragma unroll
            for (int ii = 0; ii < RT; ii++) {
                int idx = tid + 256 * ii;
                px[ii] = x4[(trow0 + (idx >> 4)) * 64 + (c + 1) * 16 + (idx & 15)];
            }
            #pragma unroll
            for (int ii = 0; ii < 4; ii++) {
                int idx = tid + 256 * ii;
                pm[ii] = mu4[(idx >> 4) * 64 + (c + 1) * 16 + (idx & 15)];
            }
        }
        // compute: 16 iterations of 4 d (2 d-pairs) each
        #pragma unroll 2
        for (int q = 0; q < 16; q++) {
            F4 mv[8], xv[RL];
            #pragma unroll
            for (int j = 0; j < 8; j++)
                mv[j].f = *(const float4*)(smu + (w * 8 + j) * PX + 4 * q);  // broadcast
            #pragma unroll
            for (int i = 0; i < RL; i++)
                xv[i].f = *(const float4*)(sx + (lane + 32 * i) * PX + 4 * q);
            #pragma unroll
            for (int i = 0; i < RL; i++)
                #pragma unroll
                for (int j = 0; j < 8; j++) {
                    acc[i * 8 + j] = fma2(xv[i].u[0], mv[j].u[0], acc[i * 8 + j]);
                    acc[i * 8 + j] = fma2(xv[i].u[1], mv[j].u[1], acc[i * 8 + j]);
                }
        }
    }

    // reduce xsq / musq across the 16 threads sharing a staging row
    #pragma unroll
    for (int o = 1; o < 16; o <<= 1) {
        #pragma unroll
        for (int ii = 0; ii < RT; ii++)
            myxsq[ii] += __shfl_xor_sync(0xffffffffu, myxsq[ii], o);
        #pragma unroll
        for (int ii = 0; ii < 4; ii++)
            mymusq[ii] += __shfl_xor_sync(0xffffffffu, mymusq[ii], o);
    }
    __syncthreads();   // everyone done reading sx before sG overlay
    if ((tid & 15) == 0) {
        #pragma unroll
        for (int ii = 0; ii < RT; ii++) sxsq[(tid >> 4) + 16 * ii] = myxsq[ii];
        #pragma unroll
        for (int ii = 0; ii < 4; ii++)  smusq[(tid >> 4) + 16 * ii] = mymusq[ii];
    }

    // dump G tile (overlay on sx, pitch PG)
    #pragma unroll
    for (int i = 0; i < RL; i++) {
        int row = lane + 32 * i;
        #pragma unroll
        for (int j = 0; j < 8; j++) {
            float2 v = unpack2(acc[i * 8 + j]);
            sG[row * PG + w * 8 + j] = v.x + v.y;
        }
    }
    __syncthreads();

    // ---- Phase B: softmax over K (ILP-restructured: level-outer shfl loops) ----
    {
        float p0 = prec[lane], p1 = prec[lane + 32];
        float pp0 = p0 * p0, pp1 = p1 * p1;
        float mq0 = smusq[lane], mq1 = smusq[lane + 32];

        float l0[RPW], l1[RPW], mx[RPW], sms[RPW];
        #pragma unroll
        for (int rr = 0; rr < RPW; rr++) {
            int row = w * RPW + rr;
            float xq = sxsq[row];
            float G0 = sG[row * PG + lane];
            float G1 = sG[row * PG + lane + 32];
            l0[rr] = -pp0 * (xq - 2.f * G0 + mq0);
            l1[rr] = -pp1 * (xq - 2.f * G1 + mq1);
            mx[rr] = fmaxf(l0[rr], l1[rr]);
        }
        #pragma unroll
        for (int o = 16; o; o >>= 1)       // 12 independent chains pipeline shfl lat
            #pragma unroll
            for (int rr = 0; rr < RPW; rr++)
                mx[rr] = fmaxf(mx[rr], __shfl_xor_sync(0xffffffffu, mx[rr], o));
        #pragma unroll
        for (int rr = 0; rr < RPW; rr++) {
            l0[rr] = __expf(l0[rr] - mx[rr]);
            l1[rr] = __expf(l1[rr] - mx[rr]);
            sms[rr] = l0[rr] + l1[rr];
        }
        #pragma unroll
        for (int o = 16; o; o >>= 1)
            #pragma unroll
            for (int rr = 0; rr < RPW; rr++)
                sms[rr] += __shfl_xor_sync(0xffffffffu, sms[rr], o);

        float ss0 = 0.f, ss1 = 0.f;
        #pragma unroll
        for (int rr = 0; rr < RPW; rr++) {
            int row = w * RPW + rr;
            float inv = 1.f / sms[rr];
            float r0 = l0[rr] * inv, r1 = l1[rr] * inv;
            sr[row * 64 + lane]      = r0;
            sr[row * 64 + lane + 32] = r1;
            ss0 += r0; ss1 += r1;
        }
        sS[w * 64 + lane]      = ss0;
        sS[w * 64 + lane + 32] = ss1;
    }
    __syncthreads();
    if (tid < 64) {      // cross-warp reduce, single deterministic slot write
        float S = 0.f;
        #pragma unroll
        for (int ww = 0; ww < 8; ww++) S += sS[ww * 64 + tid];
        g_Ssl[(b * NSLOT + slot) * 64 + tid] = S;
    }

    // ---- Phase C: pool GEMM, 8k x 8d tiles, double-buffered smem ----
    ull acc2[32];
    #pragma unroll
    for (int i = 0; i < 32; i++) acc2[i] = 0ull;

    float4* xsb[2] = { (float4*)sm, (float4*)(sm + XS1_OFF) };

    float4 pc[4];
    #pragma unroll
    for (int ii = 0; ii < 4; ii++) {
        int idx = tid + 256 * ii;
        pc[ii] = x4[(trow0 + (idx >> 6)) * 64 + (idx & 63)];
    }
    {   // prologue: fill buffer 0
        float4* xs0 = xsb[0];
        #pragma unroll
        for (int ii = 0; ii < 4; ii++) xs0[tid + 256 * ii] = pc[ii];
    }
    __syncthreads();

    for (int st = 0; st < NST; st++) {
        const float4* xs = xsb[st & 1];
        if (st + 1 < NST) {   // prefetch next stage into regs
            #pragma unroll
            for (int ii = 0; ii < 4; ii++) {
                int idx = tid + 256 * ii;
                pc[ii] = x4[(trow0 + (st + 1) * 16 + (idx >> 6)) * 64 + (idx & 63)];
            }
        }
        #pragma unroll
        for (int tt = 0; tt < 16; tt++) {
            const float* rk = &sr[(st * 16 + tt) * 64 + w * 8];
            ull rp[4];
            #pragma unroll
            for (int m = 0; m < 4; m++)
                rp[m] = *(const ull*)(rk + 2 * m);    // broadcast LDS.64
            F4 xa, xb;
            xa.f = xs[tt * 64 + lane];
            xb.f = xs[tt * 64 + 32 + lane];
            #pragma unroll
            for (int m = 0; m < 4; m++) {
                float2 rr = unpack2(rp[m]);
                ull r2a = pack2(rr.x, rr.x);
                ull r2b = pack2(rr.y, rr.y);
                int ka = (2 * m) * 4, kb = (2 * m + 1) * 4;
                acc2[ka + 0] = fma2(r2a, xa.u[0], acc2[ka + 0]);
                acc2[ka + 1] = fma2(r2a, xa.u[1], acc2[ka + 1]);
                acc2[ka + 2] = fma2(r2a, xb.u[0], acc2[ka + 2]);
                acc2[ka + 3] = fma2(r2a, xb.u[1], acc2[ka + 3]);
                acc2[kb + 0] = fma2(r2b, xa.u[0], acc2[kb + 0]);
                acc2[kb + 1] = fma2(r2b, xa.u[1], acc2[kb + 1]);
                acc2[kb + 2] = fma2(r2b, xb.u[0], acc2[kb + 2]);
                acc2[kb + 3] = fma2(r2b, xb.u[1], acc2[kb + 3]);
            }
        }
        if (st + 1 < NST) {   // store next stage into the other buffer
            float4* xn = xsb[(st + 1) & 1];
            #pragma unroll
            for (int ii = 0; ii < 4; ii++) xn[tid + 256 * ii] = pc[ii];
            __syncthreads();
        }
    }

    // STG of the partial tile into this block's private slot, L2 evict_last
    ull pol = mk_evict_last_policy();
    float4* pslot = (float4*)(g_P + (b * NSLOT + slot) * (KK * DD));
    #pragma unroll
    for (int kk = 0; kk < 8; kk++) {
        int kr = (w * 8 + kk) * 64;    // float4 row pitch = 64
        float2 a0 = unpack2(acc2[kk * 4 + 0]), a1 = unpack2(acc2[kk * 4 + 1]);
        float2 b0 = unpack2(acc2[kk * 4 + 2]), b1 = unpack2(acc2[kk * 4 + 3]);
        stg_el_f4(pslot + kr + lane,      a0.x, a0.y, a1.x, a1.y, pol);  // d = 4*lane
        stg_el_f4(pslot + kr + 32 + lane, b0.x, b0.y, b1.x, b1.y, pol);  // d = 128+4*lane
    }
}

__global__ __launch_bounds__(256, 1)
void fused_kernel(const float* __restrict__ x, const float* __restrict__ mu,
                  const float* __restrict__ prec) {
    int bx = blockIdx.x;
    if (bx < 128) {
        int b = bx >> 3, slot = bx & 7;
        fused_body<96>(b, slot, b * TT + slot * 96, x, mu, prec);
    } else {
        int b = bx - 128;
        fused_body<32>(b, 8, b * TT + 768, x, mu, prec);
    }
}

// smem: (96*68 + 64*68 + 96*64 + 96 + 64 + 512) * 4 = 70784 bytes
#define FUSED_SMEM 70784

// ---------------- finalize: out = (sum_slots P - mu*S)/(S+1e-9) -----------------
// 65536 threads, one float4 each, 9 independent slot loads (full MLP).
__global__ __launch_bounds__(256, 8)
void finalize_kernel(const float* __restrict__ mu, float* __restrict__ out) {
    int i = blockIdx.x * 256 + threadIdx.x;   // float4 index in [0, 65536)
    int b  = i >> 12;
    int k  = (i >> 6) & 63;
    int d4 = i & 63;

    const float* ss = g_Ssl + b * NSLOT * 64 + k;
    float S = 0.f;
    #pragma unroll
    for (int s = 0; s < NSLOT; s++) S += ss[s * 64];
    float inv = 1.f / (S + 1e-9f);

    const float4* pb = (const float4*)g_P + b * NSLOT * 4096 + k * 64 + d4;
    float4 a = make_float4(0.f, 0.f, 0.f, 0.f);
    #pragma unroll
    for (int s = 0; s < NSLOT; s++) {
        float4 v = pb[s * 4096];
        a.x += v.x; a.y += v.y; a.z += v.z; a.w += v.w;
    }
    float4 m = ((const float4*)mu)[k * 64 + d4];
    float4 o;
    o.x = (a.x - m.x * S) * inv;
    o.y = (a.y - m.y * S) * inv;
    o.z = (a.z - m.z * S) * inv;
    o.w = (a.w - m.w * S) * inv;
    ((float4*)out)[i] = o;
}

// ---------------- launcher --------------------------------------------------------
extern "C" void kernel_launch(void* const* d_in, const int* in_sizes, int n_in,
                              void* d_out, int out_size) {
    const float* x    = (const float*)d_in[0];
    const float* mu   = (const float*)d_in[1];
    const float* prec = (const float*)d_in[2];
    float* out = (float*)d_out;

    cudaFuncSetAttribute(fused_kernel, cudaFuncAttributeMaxDynamicSharedMemorySize,
                         FUSED_SMEM);

    fused_kernel<<<144, 256, FUSED_SMEM>>>(x, mu, prec);
    finalize_kernel<<<256, 256>>>(mu, out);
}